// round 13
// baseline (speedup 1.0000x reference)
#include <cuda_runtime.h>
#include <cuda_bf16.h>
#include <cstdint>

#define DI __device__ __forceinline__

namespace {
constexpr int S = 16384;      // tokens = 16*32*32
constexpr int C = 128;        // channels
constexpr int NUNITS = 544;   // split-KV units: 256-row tiles x 1024-key spans (uniform)
// (1/sqrt(128)) * log2(e): folded into Q so softmax uses exp2
constexpr float SCALE_LOG2E = 0.08838834764831845f * 1.4426950408889634f;
}

// cumulative units per frame: frame f has 4 tiles * (f+1) splits -> cum = 2f(f+1)
__constant__ int cU[17] = {0,4,12,24,40,60,84,112,144,180,220,264,312,364,420,480,544};

// ---------------- scratch (device globals; no allocs allowed) ----------------
__device__ __align__(128) __nv_bfloat16 g_xn[S * C];
__device__ __align__(128) __nv_bfloat16 g_q [S * C];
__device__ __align__(128) __nv_bfloat16 g_k [S * C];
__device__ __align__(128) __nv_bfloat16 g_v [S * C];
__device__ __align__(128) __nv_bfloat16 g_at[S * C];
__device__ __align__(128) __nv_bfloat16 g_wt[4][C * C];      // wt[n][k] = W[k][n]
__device__ __align__(128) float g_po[(size_t)NUNITS * 32768]; // unnormalized partial O (256x128)
__device__ __align__(128) float g_pl[NUNITS * 256];           // partial l per row

// ---------------- small PTX helpers ----------------
DI uint32_t sptr(const void* p) { return (uint32_t)__cvta_generic_to_shared(p); }
DI void cp16(uint32_t s, const void* g) {
    asm volatile("cp.async.cg.shared.global [%0], [%1], 16;\n" :: "r"(s), "l"(g));
}
DI void cp_commit() { asm volatile("cp.async.commit_group;\n" ::: "memory"); }
template<int N> DI void cp_wait() { asm volatile("cp.async.wait_group %0;\n" :: "n"(N) : "memory"); }
DI float ex2(float x) { float y; asm("ex2.approx.f32 %0, %1;" : "=f"(y) : "f"(x)); return y; }

// tile layout: rows x 128 bf16 (256B/row, 16 chunks of 16B), XOR-swizzled
DI uint32_t sw_off(int row, int ch) { return (uint32_t)(row * 256 + ((ch ^ (row & 7)) << 4)); }

DI void ldsm4(uint32_t* r, uint32_t a) {
    asm volatile("ldmatrix.sync.aligned.m8n8.x4.shared.b16 {%0,%1,%2,%3}, [%4];\n"
                 : "=r"(r[0]), "=r"(r[1]), "=r"(r[2]), "=r"(r[3]) : "r"(a));
}
DI void ldsm4t(uint32_t* r, uint32_t a) {
    asm volatile("ldmatrix.sync.aligned.m8n8.x4.trans.shared.b16 {%0,%1,%2,%3}, [%4];\n"
                 : "=r"(r[0]), "=r"(r[1]), "=r"(r[2]), "=r"(r[3]) : "r"(a));
}
DI void mma16816(float* d, const uint32_t* a, const uint32_t* b) {
    asm volatile("mma.sync.aligned.m16n8k16.row.col.f32.bf16.bf16.f32 "
                 "{%0,%1,%2,%3}, {%4,%5,%6,%7}, {%8,%9}, {%0,%1,%2,%3};\n"
                 : "+f"(d[0]), "+f"(d[1]), "+f"(d[2]), "+f"(d[3])
                 : "r"(a[0]), "r"(a[1]), "r"(a[2]), "r"(a[3]), "r"(b[0]), "r"(b[1]));
}
DI uint32_t packbf(float lo, float hi) {
    __nv_bfloat162 t = __floats2bfloat162_rn(lo, hi);
    return *reinterpret_cast<uint32_t*>(&t);
}

// async copy of an [R x 128] bf16 row-major tile into swizzled smem
template<int R, int NT>
DI void load_tile(uint32_t sbase, const __nv_bfloat16* g, int tid) {
#pragma unroll
    for (int i = 0; i < (R * 16) / NT; i++) {
        int idx = tid + i * NT;
        int row = idx >> 4, ch = idx & 15;
        cp16(sbase + sw_off(row, ch), g + row * 128 + ch * 8);
    }
}

// ---------------- 1) RMSNorm -> bf16 xn ----------------
__global__ void __launch_bounds__(256) k_norm(const float* __restrict__ x,
                                              const float* __restrict__ gamma) {
    int token = blockIdx.x * 8 + (threadIdx.x >> 5);
    int lane  = threadIdx.x & 31;
    float4 a = reinterpret_cast<const float4*>(x + token * 128)[lane];
    float ss = a.x * a.x + a.y * a.y + a.z * a.z + a.w * a.w;
#pragma unroll
    for (int m = 16; m; m >>= 1) ss += __shfl_xor_sync(0xffffffffu, ss, m);
    float sc = 11.313708498984761f / (sqrtf(ss) + 1e-8f);
    float4 gv = reinterpret_cast<const float4*>(gamma)[lane];
    __nv_bfloat162* o = reinterpret_cast<__nv_bfloat162*>(g_xn + token * 128) + lane * 2;
    o[0] = __floats2bfloat162_rn(a.x * sc * gv.x, a.y * sc * gv.y);
    o[1] = __floats2bfloat162_rn(a.z * sc * gv.z, a.w * sc * gv.w);
}

// ---------------- 2) weight transpose + bf16 convert ----------------
__global__ void __launch_bounds__(256) k_wconv(const float* __restrict__ wq,
                                               const float* __restrict__ wk,
                                               const float* __restrict__ wv,
                                               const float* __restrict__ wo) {
    const float* src = blockIdx.y == 0 ? wq : blockIdx.y == 1 ? wk
                     : blockIdx.y == 2 ? wv : wo;
    int idx = blockIdx.x * 256 + threadIdx.x;
    int n = idx >> 7, k = idx & 127;
    g_wt[blockIdx.y][idx] = __float2bfloat16(src[k * 128 + n]);
}

// ---------------- 3) QKV projection GEMM (bf16 mma) ----------------
__global__ void __launch_bounds__(256) k_qkv(const float* __restrict__ bq,
                                             const float* __restrict__ bk,
                                             const float* __restrict__ bv) {
    extern __shared__ __align__(1024) char smem[];
    uint32_t sA = sptr(smem), sB = sA + 128 * 256;
    int which = blockIdx.y;
    int tid = threadIdx.x, wid = tid >> 5, lane = tid & 31;
    load_tile<128, 256>(sA, g_xn + blockIdx.x * 128 * 128, tid);
    load_tile<128, 256>(sB, g_wt[which], tid);
    cp_commit(); cp_wait<0>(); __syncthreads();
    int agrp = lane >> 3, lr = lane & 7;
    int mrow = wid * 16 + lr + ((agrp & 1) << 3);
    float acc[16][4];
#pragma unroll
    for (int i = 0; i < 16; i++) { acc[i][0] = acc[i][1] = acc[i][2] = acc[i][3] = 0.f; }
#pragma unroll
    for (int kk2 = 0; kk2 < 4; kk2++) {
        uint32_t a0[4], a1[4];
        ldsm4(a0, sA + sw_off(mrow, 4 * kk2 +     (agrp >> 1)));
        ldsm4(a1, sA + sw_off(mrow, 4 * kk2 + 2 + (agrp >> 1)));
#pragma unroll
        for (int nt = 0; nt < 16; nt++) {
            uint32_t b[4];
            ldsm4(b, sB + sw_off(nt * 8 + lr, 4 * kk2 + agrp));
            mma16816(acc[nt], a0, b);
            mma16816(acc[nt], a1, b + 2);
        }
    }
    const float* bias = which == 0 ? bq : which == 1 ? bk : bv;
    __nv_bfloat16* out = which == 0 ? g_q : which == 1 ? g_k : g_v;
    float mul = (which == 0) ? SCALE_LOG2E : 1.0f;   // fold softmax scale into Q
    int r0 = blockIdx.x * 128 + wid * 16 + (lane >> 2);
    int cb = (lane & 3) * 2;
#pragma unroll
    for (int nt = 0; nt < 16; nt++) {
        int col = nt * 8 + cb;
        float b0 = bias[col], b1 = bias[col + 1];
        *reinterpret_cast<__nv_bfloat162*>(out + r0 * 128 + col) =
            __floats2bfloat162_rn((acc[nt][0] + b0) * mul, (acc[nt][1] + b1) * mul);
        *reinterpret_cast<__nv_bfloat162*>(out + (r0 + 8) * 128 + col) =
            __floats2bfloat162_rn((acc[nt][2] + b0) * mul, (acc[nt][3] + b1) * mul);
    }
}

// ---------------- 4) split-KV flash attention (m32 warps, fixed-max) ----------------
// CTA = 256-row Q-tile, 8 warps x 32 rows, 64-key chunks, ring-3 K/V.
// Each K/V B-fragment feeds 4 MMAs (two 16-row A-frags) -> LDS/tensor ratio 0.62.
// Fixed-max softmax; softmax interleaved with PV at half-chunk granularity.
__global__ void __launch_bounds__(256, 1) k_attn() {
    extern __shared__ __align__(1024) char smem[];
    uint32_t sQ = sptr(smem);
    uint32_t sK[3], sV[3];
#pragma unroll
    for (int st = 0; st < 3; st++) {
        sK[st] = sQ + 65536 + st * 32768;
        sV[st] = sK[st] + 16384;
    }
    int tid = threadIdx.x, wid = tid >> 5, lane = tid & 31;
    int agrp = lane >> 3, lr = lane & 7;

    // decode unit: uniform 16-chunk spans
    int u = NUNITS - 1 - (int)blockIdx.x;
    int f = 0;
#pragma unroll
    for (int i = 0; i < 16; i++) if (u >= cU[i + 1]) f = i + 1;
    int r   = u - cU[f];
    int ns  = f + 1;
    int tif = r / ns;
    int sp  = r - tif * ns;
    int q0  = (f * 4 + tif) * 256;
    int kc0 = sp * 16;                    // 16 chunks of 64 keys, always full

    // prologue: Q + chunk0 in G0, chunk1 in G1
    load_tile<256, 256>(sQ, g_q + (size_t)q0 * 128, tid);
    load_tile<64, 256>(sK[0], g_k + (size_t)kc0 * 8192, tid);
    load_tile<64, 256>(sV[0], g_v + (size_t)kc0 * 8192, tid);
    cp_commit();
    load_tile<64, 256>(sK[1], g_k + (size_t)(kc0 + 1) * 8192, tid);
    load_tile<64, 256>(sV[1], g_v + (size_t)(kc0 + 1) * 8192, tid);
    cp_commit();
    cp_wait<1>();
    __syncthreads();

    int mrowA = wid * 32 + lr + ((agrp & 1) << 3);   // rows of A-frag 0; +16 for frag 1
    float oA[16][4], oB[16][4];
#pragma unroll
    for (int j = 0; j < 16; j++) {
        oA[j][0] = oA[j][1] = oA[j][2] = oA[j][3] = 0.f;
        oB[j][0] = oB[j][1] = oB[j][2] = oB[j][3] = 0.f;
    }
    float lA0 = 0.f, lA1 = 0.f, lB0 = 0.f, lB1 = 0.f;

    for (int i = 0; i < 16; i++) {
        __syncthreads();                   // all warps done with slot (i+2)%3
        if (i + 2 < 16) {
            int st = (i + 2) % 3;
            load_tile<64, 256>(sK[st], g_k + (size_t)(kc0 + i + 2) * 8192, tid);
            load_tile<64, 256>(sV[st], g_v + (size_t)(kc0 + i + 2) * 8192, tid);
        }
        cp_commit();
        cp_wait<1>();                      // chunk i+1 resident (i resident since last iter)
        uint32_t kb = sK[i % 3], vb = sV[i % 3];

        // ---- S = Q @ K^T : 32 rows x 64 keys ----
        float s[8][8];
#pragma unroll
        for (int nt = 0; nt < 8; nt++)
#pragma unroll
            for (int c = 0; c < 8; c++) s[nt][c] = 0.f;
#pragma unroll
        for (int kk2 = 0; kk2 < 4; kk2++) {
            uint32_t a0A[4], a1A[4], a0B[4], a1B[4];
            ldsm4(a0A, sQ + sw_off(mrowA,      4 * kk2 +     (agrp >> 1)));
            ldsm4(a1A, sQ + sw_off(mrowA,      4 * kk2 + 2 + (agrp >> 1)));
            ldsm4(a0B, sQ + sw_off(mrowA + 16, 4 * kk2 +     (agrp >> 1)));
            ldsm4(a1B, sQ + sw_off(mrowA + 16, 4 * kk2 + 2 + (agrp >> 1)));
#pragma unroll
            for (int nt = 0; nt < 8; nt++) {
                uint32_t b[4];
                ldsm4(b, kb + sw_off(nt * 8 + lr, 4 * kk2 + agrp));
                mma16816(s[nt],     a0A, b);
                mma16816(s[nt],     a1A, b + 2);
                mma16816(s[nt] + 4, a0B, b);
                mma16816(s[nt] + 4, a1B, b + 2);
            }
        }

        // ---- softmax + PV, interleaved per 32-key half ----
#pragma unroll
        for (int h = 0; h < 2; h++) {
            uint32_t pfA[2][4], pfB[2][4];
#pragma unroll
            for (int nt4 = 0; nt4 < 4; nt4++) {
                int nt = h * 4 + nt4;
                float p0 = ex2(s[nt][0]), p1 = ex2(s[nt][1]);
                float p2 = ex2(s[nt][2]), p3 = ex2(s[nt][3]);
                float r0 = ex2(s[nt][4]), r1 = ex2(s[nt][5]);
                float r2 = ex2(s[nt][6]), r3 = ex2(s[nt][7]);
                lA0 += p0 + p1;  lA1 += p2 + p3;
                lB0 += r0 + r1;  lB1 += r2 + r3;
                int kk = nt4 >> 1;
                if ((nt4 & 1) == 0) {
                    pfA[kk][0] = packbf(p0, p1); pfA[kk][1] = packbf(p2, p3);
                    pfB[kk][0] = packbf(r0, r1); pfB[kk][1] = packbf(r2, r3);
                } else {
                    pfA[kk][2] = packbf(p0, p1); pfA[kk][3] = packbf(p2, p3);
                    pfB[kk][2] = packbf(r0, r1); pfB[kk][3] = packbf(r2, r3);
                }
            }
#pragma unroll
            for (int j = 0; j < 16; j++) {
                uint32_t vv[4];
                ldsm4t(vv, vb + sw_off(h * 32 + agrp * 8 + lr, j));
                mma16816(oA[j], pfA[0], vv);
                mma16816(oA[j], pfA[1], vv + 2);
                mma16816(oB[j], pfB[0], vv);
                mma16816(oB[j], pfB[1], vv + 2);
            }
        }
    }

    // ---- epilogue: quad-reduce l, store unnormalized partials ----
    lA0 += __shfl_xor_sync(0xffffffffu, lA0, 1);
    lA0 += __shfl_xor_sync(0xffffffffu, lA0, 2);
    lA1 += __shfl_xor_sync(0xffffffffu, lA1, 1);
    lA1 += __shfl_xor_sync(0xffffffffu, lA1, 2);
    lB0 += __shfl_xor_sync(0xffffffffu, lB0, 1);
    lB0 += __shfl_xor_sync(0xffffffffu, lB0, 2);
    lB1 += __shfl_xor_sync(0xffffffffu, lB1, 1);
    lB1 += __shfl_xor_sync(0xffffffffu, lB1, 2);
    int rA = wid * 32 + (lane >> 2);
    int cb = (lane & 3) * 2;
    float* po = g_po + (size_t)u * 32768;
#pragma unroll
    for (int j = 0; j < 16; j++) {
        int col = j * 8 + cb;
        *reinterpret_cast<float2*>(po + (rA)      * 128 + col) = make_float2(oA[j][0], oA[j][1]);
        *reinterpret_cast<float2*>(po + (rA + 8)  * 128 + col) = make_float2(oA[j][2], oA[j][3]);
        *reinterpret_cast<float2*>(po + (rA + 16) * 128 + col) = make_float2(oB[j][0], oB[j][1]);
        *reinterpret_cast<float2*>(po + (rA + 24) * 128 + col) = make_float2(oB[j][2], oB[j][3]);
    }
    if ((lane & 3) == 0) {
        g_pl[u * 256 + rA]      = lA0;
        g_pl[u * 256 + rA + 8]  = lA1;
        g_pl[u * 256 + rA + 16] = lB0;
        g_pl[u * 256 + rA + 24] = lB1;
    }
}

// ---------------- 4b) combine (plain sums) ----------------
// grid 256: block b -> tile t=b>>2 (256 rows), row-quarter b&3.
__global__ void __launch_bounds__(256) k_comb() {
    int b  = blockIdx.x;
    int t  = b >> 2;
    int f  = t >> 2;
    int ns = f + 1;
    int ub = cU[f] + (t & 3) * ns;
    int row = (b & 3) * 64 + (threadIdx.x >> 2);
    int c0  = (threadIdx.x & 3) * 32;
    float l = 0.f;
    for (int s = 0; s < ns; s++) l += g_pl[(ub + s) * 256 + row];
    float inv = 1.f / l;
    float4 acc[8];
#pragma unroll
    for (int j = 0; j < 8; j++) acc[j] = make_float4(0.f, 0.f, 0.f, 0.f);
    for (int s = 0; s < ns; s++) {
        const float4* p = reinterpret_cast<const float4*>(
            g_po + (size_t)(ub + s) * 32768 + (size_t)row * 128 + c0);
#pragma unroll
        for (int j = 0; j < 8; j++) {
            float4 v = p[j];
            acc[j].x += v.x; acc[j].y += v.y; acc[j].z += v.z; acc[j].w += v.w;
        }
    }
    __nv_bfloat162* dst = reinterpret_cast<__nv_bfloat162*>(
        g_at + (size_t)(t * 256 + row) * 128 + c0);
#pragma unroll
    for (int j = 0; j < 8; j++) {
        dst[2 * j]     = __floats2bfloat162_rn(acc[j].x * inv, acc[j].y * inv);
        dst[2 * j + 1] = __floats2bfloat162_rn(acc[j].z * inv, acc[j].w * inv);
    }
}

// ---------------- 5) output projection + bias + residual ----------------
__global__ void __launch_bounds__(256) k_oproj(const float* __restrict__ bo,
                                               const float* __restrict__ x,
                                               float* __restrict__ out) {
    extern __shared__ __align__(1024) char smem[];
    uint32_t sA = sptr(smem), sB = sA + 128 * 256;
    int tid = threadIdx.x, wid = tid >> 5, lane = tid & 31;
    load_tile<128, 256>(sA, g_at + blockIdx.x * 128 * 128, tid);
    load_tile<128, 256>(sB, g_wt[3], tid);
    cp_commit(); cp_wait<0>(); __syncthreads();
    int agrp = lane >> 3, lr = lane & 7;
    int mrow = wid * 16 + lr + ((agrp & 1) << 3);
    float acc[16][4];
#pragma unroll
    for (int i = 0; i < 16; i++) { acc[i][0] = acc[i][1] = acc[i][2] = acc[i][3] = 0.f; }
#pragma unroll
    for (int kk2 = 0; kk2 < 4; kk2++) {
        uint32_t a0[4], a1[4];
        ldsm4(a0, sA + sw_off(mrow, 4 * kk2 +     (agrp >> 1)));
        ldsm4(a1, sA + sw_off(mrow, 4 * kk2 + 2 + (agrp >> 1)));
#pragma unroll
        for (int nt = 0; nt < 16; nt++) {
            uint32_t b[4];
            ldsm4(b, sB + sw_off(nt * 8 + lr, 4 * kk2 + agrp));
            mma16816(acc[nt], a0, b);
            mma16816(acc[nt], a1, b + 2);
        }
    }
    int r0 = blockIdx.x * 128 + wid * 16 + (lane >> 2);
    int cb = (lane & 3) * 2;
#pragma unroll
    for (int nt = 0; nt < 16; nt++) {
        int col = nt * 8 + cb;
        float b0 = bo[col], b1 = bo[col + 1];
        *reinterpret_cast<float2*>(out + r0 * 128 + col) =
            make_float2(acc[nt][0] + b0 + x[r0 * 128 + col],
                        acc[nt][1] + b1 + x[r0 * 128 + col + 1]);
        *reinterpret_cast<float2*>(out + (r0 + 8) * 128 + col) =
            make_float2(acc[nt][2] + b0 + x[(r0 + 8) * 128 + col],
                        acc[nt][3] + b1 + x[(r0 + 8) * 128 + col + 1]);
    }
}

// ---------------- launch ----------------
extern "C" void kernel_launch(void* const* d_in, const int* in_sizes, int n_in,
                              void* d_out, int out_size) {
    (void)in_sizes; (void)n_in; (void)out_size;
    const float* x     = (const float*)d_in[0];
    const float* gamma = (const float*)d_in[1];
    const float* wq = (const float*)d_in[2];
    const float* bq = (const float*)d_in[3];
    const float* wk = (const float*)d_in[4];
    const float* bk = (const float*)d_in[5];
    const float* wv = (const float*)d_in[6];
    const float* bv = (const float*)d_in[7];
    const float* wo = (const float*)d_in[8];
    const float* bo = (const float*)d_in[9];
    float* out = (float*)d_out;

    cudaFuncSetAttribute(k_qkv,   cudaFuncAttributeMaxDynamicSharedMemorySize, 65536);
    cudaFuncSetAttribute(k_oproj, cudaFuncAttributeMaxDynamicSharedMemorySize, 65536);
    cudaFuncSetAttribute(k_attn,  cudaFuncAttributeMaxDynamicSharedMemorySize, 163840);

    k_norm <<<S / 8, 256>>>(x, gamma);
    k_wconv<<<dim3(64, 4), 256>>>(wq, wk, wv, wo);
    k_qkv  <<<dim3(S / 128, 3), 256, 65536>>>(bq, bk, bv);
    k_attn <<<NUNITS, 256, 163840>>>();
    k_comb <<<256, 256>>>();
    k_oproj<<<S / 128, 256, 65536>>>(bo, x, out);
}

// round 14
// speedup vs baseline: 1.0228x; 1.0228x over previous
#include <cuda_runtime.h>
#include <cuda_bf16.h>
#include <cuda_fp16.h>
#include <cstdint>

#define DI __device__ __forceinline__

namespace {
constexpr int S = 16384;      // tokens = 16*32*32
constexpr int C = 128;        // channels
constexpr int NUNITS = 544;   // split-KV units: 256-row tiles x 1024-key spans (uniform)
// (1/sqrt(128)) * log2(e): folded into Q so softmax uses exp2
constexpr float SCALE_LOG2E = 0.08838834764831845f * 1.4426950408889634f;
}

// cumulative units per frame: frame f has 4 tiles * (f+1) splits -> cum = 2f(f+1)
__constant__ int cU[17] = {0,4,12,24,40,60,84,112,144,180,220,264,312,364,420,480,544};

// ---------------- scratch (device globals; no allocs allowed) ----------------
__device__ __align__(128) __nv_bfloat16 g_xn[S * C];
__device__ __align__(128) __nv_bfloat16 g_q [S * C];
__device__ __align__(128) __nv_bfloat16 g_k [S * C];
__device__ __align__(128) __half        g_v [S * C];          // V in f16 (PV runs f16 mma)
__device__ __align__(128) __nv_bfloat16 g_at[S * C];
__device__ __align__(128) __nv_bfloat16 g_wt[4][C * C];       // wt[n][k] = W[k][n]
__device__ __align__(128) __nv_bfloat16 g_po[(size_t)NUNITS * 32768]; // partial O (bf16)
__device__ __align__(128) float g_pl[NUNITS * 256];           // partial l per row

// ---------------- small PTX helpers ----------------
DI uint32_t sptr(const void* p) { return (uint32_t)__cvta_generic_to_shared(p); }
DI void cp16(uint32_t s, const void* g) {
    asm volatile("cp.async.cg.shared.global [%0], [%1], 16;\n" :: "r"(s), "l"(g));
}
DI void cp_commit() { asm volatile("cp.async.commit_group;\n" ::: "memory"); }
template<int N> DI void cp_wait() { asm volatile("cp.async.wait_group %0;\n" :: "n"(N) : "memory"); }
DI uint32_t ex2h2(uint32_t x) {       // ex2.approx on a packed f16x2
    uint32_t y;
    asm("ex2.approx.f16x2 %0, %1;" : "=r"(y) : "r"(x));
    return y;
}
DI uint32_t packh2(float lo, float hi) {
    __half2 t = __floats2half2_rn(lo, hi);
    return *reinterpret_cast<uint32_t*>(&t);
}

// tile layout: rows x 128 x16-bit (256B/row, 16 chunks of 16B), XOR-swizzled
DI uint32_t sw_off(int row, int ch) { return (uint32_t)(row * 256 + ((ch ^ (row & 7)) << 4)); }

DI void ldsm4(uint32_t* r, uint32_t a) {
    asm volatile("ldmatrix.sync.aligned.m8n8.x4.shared.b16 {%0,%1,%2,%3}, [%4];\n"
                 : "=r"(r[0]), "=r"(r[1]), "=r"(r[2]), "=r"(r[3]) : "r"(a));
}
DI void ldsm4t(uint32_t* r, uint32_t a) {
    asm volatile("ldmatrix.sync.aligned.m8n8.x4.trans.shared.b16 {%0,%1,%2,%3}, [%4];\n"
                 : "=r"(r[0]), "=r"(r[1]), "=r"(r[2]), "=r"(r[3]) : "r"(a));
}
DI void mma16816(float* d, const uint32_t* a, const uint32_t* b) {   // bf16
    asm volatile("mma.sync.aligned.m16n8k16.row.col.f32.bf16.bf16.f32 "
                 "{%0,%1,%2,%3}, {%4,%5,%6,%7}, {%8,%9}, {%0,%1,%2,%3};\n"
                 : "+f"(d[0]), "+f"(d[1]), "+f"(d[2]), "+f"(d[3])
                 : "r"(a[0]), "r"(a[1]), "r"(a[2]), "r"(a[3]), "r"(b[0]), "r"(b[1]));
}
DI void mma_h(float* d, const uint32_t* a, const uint32_t* b) {      // f16
    asm volatile("mma.sync.aligned.m16n8k16.row.col.f32.f16.f16.f32 "
                 "{%0,%1,%2,%3}, {%4,%5,%6,%7}, {%8,%9}, {%0,%1,%2,%3};\n"
                 : "+f"(d[0]), "+f"(d[1]), "+f"(d[2]), "+f"(d[3])
                 : "r"(a[0]), "r"(a[1]), "r"(a[2]), "r"(a[3]), "r"(b[0]), "r"(b[1]));
}

// async copy of an [R x 128] 16-bit row-major tile into swizzled smem
template<int R, int NT>
DI void load_tile(uint32_t sbase, const __nv_bfloat16* g, int tid) {
#pragma unroll
    for (int i = 0; i < (R * 16) / NT; i++) {
        int idx = tid + i * NT;
        int row = idx >> 4, ch = idx & 15;
        cp16(sbase + sw_off(row, ch), g + row * 128 + ch * 8);
    }
}

// ---------------- 1) RMSNorm -> bf16 xn ----------------
__global__ void __launch_bounds__(256) k_norm(const float* __restrict__ x,
                                              const float* __restrict__ gamma) {
    int token = blockIdx.x * 8 + (threadIdx.x >> 5);
    int lane  = threadIdx.x & 31;
    float4 a = reinterpret_cast<const float4*>(x + token * 128)[lane];
    float ss = a.x * a.x + a.y * a.y + a.z * a.z + a.w * a.w;
#pragma unroll
    for (int m = 16; m; m >>= 1) ss += __shfl_xor_sync(0xffffffffu, ss, m);
    float sc = 11.313708498984761f / (sqrtf(ss) + 1e-8f);
    float4 gv = reinterpret_cast<const float4*>(gamma)[lane];
    __nv_bfloat162* o = reinterpret_cast<__nv_bfloat162*>(g_xn + token * 128) + lane * 2;
    o[0] = __floats2bfloat162_rn(a.x * sc * gv.x, a.y * sc * gv.y);
    o[1] = __floats2bfloat162_rn(a.z * sc * gv.z, a.w * sc * gv.w);
}

// ---------------- 2) weight transpose + bf16 convert ----------------
__global__ void __launch_bounds__(256) k_wconv(const float* __restrict__ wq,
                                               const float* __restrict__ wk,
                                               const float* __restrict__ wv,
                                               const float* __restrict__ wo) {
    const float* src = blockIdx.y == 0 ? wq : blockIdx.y == 1 ? wk
                     : blockIdx.y == 2 ? wv : wo;
    int idx = blockIdx.x * 256 + threadIdx.x;
    int n = idx >> 7, k = idx & 127;
    g_wt[blockIdx.y][idx] = __float2bfloat16(src[k * 128 + n]);
}

// ---------------- 3) QKV projection GEMM (bf16 mma; V written as f16) ----------------
__global__ void __launch_bounds__(256) k_qkv(const float* __restrict__ bq,
                                             const float* __restrict__ bk,
                                             const float* __restrict__ bv) {
    extern __shared__ __align__(1024) char smem[];
    uint32_t sA = sptr(smem), sB = sA + 128 * 256;
    int which = blockIdx.y;
    int tid = threadIdx.x, wid = tid >> 5, lane = tid & 31;
    load_tile<128, 256>(sA, g_xn + blockIdx.x * 128 * 128, tid);
    load_tile<128, 256>(sB, g_wt[which], tid);
    cp_commit(); cp_wait<0>(); __syncthreads();
    int agrp = lane >> 3, lr = lane & 7;
    int mrow = wid * 16 + lr + ((agrp & 1) << 3);
    float acc[16][4];
#pragma unroll
    for (int i = 0; i < 16; i++) { acc[i][0] = acc[i][1] = acc[i][2] = acc[i][3] = 0.f; }
#pragma unroll
    for (int kk2 = 0; kk2 < 4; kk2++) {
        uint32_t a0[4], a1[4];
        ldsm4(a0, sA + sw_off(mrow, 4 * kk2 +     (agrp >> 1)));
        ldsm4(a1, sA + sw_off(mrow, 4 * kk2 + 2 + (agrp >> 1)));
#pragma unroll
        for (int nt = 0; nt < 16; nt++) {
            uint32_t b[4];
            ldsm4(b, sB + sw_off(nt * 8 + lr, 4 * kk2 + agrp));
            mma16816(acc[nt], a0, b);
            mma16816(acc[nt], a1, b + 2);
        }
    }
    const float* bias = which == 0 ? bq : which == 1 ? bk : bv;
    int r0 = blockIdx.x * 128 + wid * 16 + (lane >> 2);
    int cb = (lane & 3) * 2;
#pragma unroll
    for (int nt = 0; nt < 16; nt++) {
        int col = nt * 8 + cb;
        float b0 = bias[col], b1 = bias[col + 1];
        if (which == 2) {   // V -> f16
            *reinterpret_cast<__half2*>(g_v + (size_t)r0 * 128 + col) =
                __floats2half2_rn(acc[nt][0] + b0, acc[nt][1] + b1);
            *reinterpret_cast<__half2*>(g_v + (size_t)(r0 + 8) * 128 + col) =
                __floats2half2_rn(acc[nt][2] + b0, acc[nt][3] + b1);
        } else {
            __nv_bfloat16* out = which == 0 ? g_q : g_k;
            float mul = (which == 0) ? SCALE_LOG2E : 1.0f;
            *reinterpret_cast<__nv_bfloat162*>(out + (size_t)r0 * 128 + col) =
                __floats2bfloat162_rn((acc[nt][0] + b0) * mul, (acc[nt][1] + b1) * mul);
            *reinterpret_cast<__nv_bfloat162*>(out + (size_t)(r0 + 8) * 128 + col) =
                __floats2bfloat162_rn((acc[nt][2] + b0) * mul, (acc[nt][3] + b1) * mul);
        }
    }
}

// ---------------- 4) split-KV flash attention (m32 warps, f16x2 softmax) ----------------
// CTA = 256-row Q-tile, 8 warps x 32 rows, 64-key chunks, ring-3 K/V.
// Per chunk: two 32-key micro-phases QK->softmax->PV; softmax = ex2.approx.f16x2
// whose half2 output IS the PV A-fragment (P and V in f16).
__global__ void __launch_bounds__(256, 1) k_attn() {
    extern __shared__ __align__(1024) char smem[];
    uint32_t sQ = sptr(smem);
    uint32_t sK[3], sV[3];
#pragma unroll
    for (int st = 0; st < 3; st++) {
        sK[st] = sQ + 65536 + st * 32768;
        sV[st] = sK[st] + 16384;
    }
    int tid = threadIdx.x, wid = tid >> 5, lane = tid & 31;
    int agrp = lane >> 3, lr = lane & 7;

    int u = NUNITS - 1 - (int)blockIdx.x;
    int f = 0;
#pragma unroll
    for (int i = 0; i < 16; i++) if (u >= cU[i + 1]) f = i + 1;
    int r   = u - cU[f];
    int ns  = f + 1;
    int tif = r / ns;
    int sp  = r - tif * ns;
    int q0  = (f * 4 + tif) * 256;
    int kc0 = sp * 16;                    // 16 chunks of 64 keys, always full

    load_tile<256, 256>(sQ, g_q + (size_t)q0 * 128, tid);
    load_tile<64, 256>(sK[0], g_k + (size_t)kc0 * 8192, tid);
    load_tile<64, 256>(sV[0], reinterpret_cast<const __nv_bfloat16*>(g_v) + (size_t)kc0 * 8192, tid);
    cp_commit();
    load_tile<64, 256>(sK[1], g_k + (size_t)(kc0 + 1) * 8192, tid);
    load_tile<64, 256>(sV[1], reinterpret_cast<const __nv_bfloat16*>(g_v) + (size_t)(kc0 + 1) * 8192, tid);
    cp_commit();
    cp_wait<1>();
    __syncthreads();

    int mrowA = wid * 32 + lr + ((agrp & 1) << 3);   // rows of A-frag 0; +16 for frag 1
    float oA[16][4], oB[16][4];
#pragma unroll
    for (int j = 0; j < 16; j++) {
        oA[j][0] = oA[j][1] = oA[j][2] = oA[j][3] = 0.f;
        oB[j][0] = oB[j][1] = oB[j][2] = oB[j][3] = 0.f;
    }
    float lA0 = 0.f, lA1 = 0.f, lB0 = 0.f, lB1 = 0.f;

    for (int i = 0; i < 16; i++) {
        __syncthreads();                   // all warps done with slot (i+2)%3
        if (i + 2 < 16) {
            int st = (i + 2) % 3;
            load_tile<64, 256>(sK[st], g_k + (size_t)(kc0 + i + 2) * 8192, tid);
            load_tile<64, 256>(sV[st],
                reinterpret_cast<const __nv_bfloat16*>(g_v) + (size_t)(kc0 + i + 2) * 8192, tid);
        }
        cp_commit();
        cp_wait<1>();                      // chunk i+1 resident (i resident since last iter)
        uint32_t kb = sK[i % 3], vb = sV[i % 3];

#pragma unroll
        for (int h = 0; h < 2; h++) {      // 32-key micro-phase
            // ---- S = Q @ K^T : 32 rows x 32 keys ----
            float s[4][8];
#pragma unroll
            for (int nt4 = 0; nt4 < 4; nt4++)
#pragma unroll
                for (int c = 0; c < 8; c++) s[nt4][c] = 0.f;
#pragma unroll
            for (int kk2 = 0; kk2 < 4; kk2++) {
                uint32_t a0A[4], a1A[4], a0B[4], a1B[4];
                ldsm4(a0A, sQ + sw_off(mrowA,      4 * kk2 +     (agrp >> 1)));
                ldsm4(a1A, sQ + sw_off(mrowA,      4 * kk2 + 2 + (agrp >> 1)));
                ldsm4(a0B, sQ + sw_off(mrowA + 16, 4 * kk2 +     (agrp >> 1)));
                ldsm4(a1B, sQ + sw_off(mrowA + 16, 4 * kk2 + 2 + (agrp >> 1)));
#pragma unroll
                for (int nt4 = 0; nt4 < 4; nt4++) {
                    uint32_t b[4];
                    ldsm4(b, kb + sw_off((h * 4 + nt4) * 8 + lr, 4 * kk2 + agrp));
                    mma16816(s[nt4],     a0A, b);
                    mma16816(s[nt4],     a1A, b + 2);
                    mma16816(s[nt4] + 4, a0B, b);
                    mma16816(s[nt4] + 4, a1B, b + 2);
                }
            }
            // ---- softmax: cvt f32x2 -> ex2.f16x2; result = PV A-fragment ----
            uint32_t pfA[2][4], pfB[2][4];
            __half2 hA0 = __floats2half2_rn(0.f, 0.f), hA1 = hA0, hB0 = hA0, hB1 = hA0;
#pragma unroll
            for (int nt4 = 0; nt4 < 4; nt4++) {
                uint32_t pA0 = ex2h2(packh2(s[nt4][0], s[nt4][1]));
                uint32_t pA1 = ex2h2(packh2(s[nt4][2], s[nt4][3]));
                uint32_t pB0 = ex2h2(packh2(s[nt4][4], s[nt4][5]));
                uint32_t pB1 = ex2h2(packh2(s[nt4][6], s[nt4][7]));
                hA0 = __hadd2(hA0, *reinterpret_cast<__half2*>(&pA0));
                hA1 = __hadd2(hA1, *reinterpret_cast<__half2*>(&pA1));
                hB0 = __hadd2(hB0, *reinterpret_cast<__half2*>(&pB0));
                hB1 = __hadd2(hB1, *reinterpret_cast<__half2*>(&pB1));
                int kk = nt4 >> 1;
                if ((nt4 & 1) == 0) {
                    pfA[kk][0] = pA0; pfA[kk][1] = pA1;
                    pfB[kk][0] = pB0; pfB[kk][1] = pB1;
                } else {
                    pfA[kk][2] = pA0; pfA[kk][3] = pA1;
                    pfB[kk][2] = pB0; pfB[kk][3] = pB1;
                }
            }
            { float2 t;
              t = __half22float2(hA0); lA0 += t.x + t.y;
              t = __half22float2(hA1); lA1 += t.x + t.y;
              t = __half22float2(hB0); lB0 += t.x + t.y;
              t = __half22float2(hB1); lB1 += t.x + t.y; }
            // ---- O += P @ V (f16 x f16) ----
#pragma unroll
            for (int j = 0; j < 16; j++) {
                uint32_t vv[4];
                ldsm4t(vv, vb + sw_off(h * 32 + agrp * 8 + lr, j));
                mma_h(oA[j], pfA[0], vv);
                mma_h(oA[j], pfA[1], vv + 2);
                mma_h(oB[j], pfB[0], vv);
                mma_h(oB[j], pfB[1], vv + 2);
            }
        }
    }

    // ---- epilogue: quad-reduce l, store unnormalized partials (bf16) ----
    lA0 += __shfl_xor_sync(0xffffffffu, lA0, 1);
    lA0 += __shfl_xor_sync(0xffffffffu, lA0, 2);
    lA1 += __shfl_xor_sync(0xffffffffu, lA1, 1);
    lA1 += __shfl_xor_sync(0xffffffffu, lA1, 2);
    lB0 += __shfl_xor_sync(0xffffffffu, lB0, 1);
    lB0 += __shfl_xor_sync(0xffffffffu, lB0, 2);
    lB1 += __shfl_xor_sync(0xffffffffu, lB1, 1);
    lB1 += __shfl_xor_sync(0xffffffffu, lB1, 2);
    int rA = wid * 32 + (lane >> 2);
    int cb = (lane & 3) * 2;
    __nv_bfloat16* po = g_po + (size_t)u * 32768;
#pragma unroll
    for (int j = 0; j < 16; j++) {
        int col = j * 8 + cb;
        *reinterpret_cast<__nv_bfloat162*>(po + (size_t)(rA)      * 128 + col) =
            __floats2bfloat162_rn(oA[j][0], oA[j][1]);
        *reinterpret_cast<__nv_bfloat162*>(po + (size_t)(rA + 8)  * 128 + col) =
            __floats2bfloat162_rn(oA[j][2], oA[j][3]);
        *reinterpret_cast<__nv_bfloat162*>(po + (size_t)(rA + 16) * 128 + col) =
            __floats2bfloat162_rn(oB[j][0], oB[j][1]);
        *reinterpret_cast<__nv_bfloat162*>(po + (size_t)(rA + 24) * 128 + col) =
            __floats2bfloat162_rn(oB[j][2], oB[j][3]);
    }
    if ((lane & 3) == 0) {
        g_pl[u * 256 + rA]      = lA0;
        g_pl[u * 256 + rA + 8]  = lA1;
        g_pl[u * 256 + rA + 16] = lB0;
        g_pl[u * 256 + rA + 24] = lB1;
    }
}

// ---------------- 4b) combine (plain sums over bf16 partials) ----------------
// grid 256: block b -> tile t=b>>2 (256 rows), row-quarter b&3.
__global__ void __launch_bounds__(256) k_comb() {
    int b  = blockIdx.x;
    int t  = b >> 2;
    int f  = t >> 2;
    int ns = f + 1;
    int ub = cU[f] + (t & 3) * ns;
    int row = (b & 3) * 64 + (threadIdx.x >> 2);
    int c0  = (threadIdx.x & 3) * 32;
    float l = 0.f;
    for (int s = 0; s < ns; s++) l += g_pl[(ub + s) * 256 + row];
    float inv = 1.f / l;
    float acc[32];
#pragma unroll
    for (int j = 0; j < 32; j++) acc[j] = 0.f;
    for (int s = 0; s < ns; s++) {
        const __nv_bfloat162* p = reinterpret_cast<const __nv_bfloat162*>(
            g_po + (size_t)(ub + s) * 32768 + (size_t)row * 128 + c0);
#pragma unroll
        for (int j = 0; j < 16; j++) {
            float2 v = __bfloat1622float2(p[j]);
            acc[2 * j] += v.x;  acc[2 * j + 1] += v.y;
        }
    }
    __nv_bfloat162* dst = reinterpret_cast<__nv_bfloat162*>(
        g_at + (size_t)(t * 256 + row) * 128 + c0);
#pragma unroll
    for (int j = 0; j < 16; j++)
        dst[j] = __floats2bfloat162_rn(acc[2 * j] * inv, acc[2 * j + 1] * inv);
}

// ---------------- 5) output projection + bias + residual ----------------
__global__ void __launch_bounds__(256) k_oproj(const float* __restrict__ bo,
                                               const float* __restrict__ x,
                                               float* __restrict__ out) {
    extern __shared__ __align__(1024) char smem[];
    uint32_t sA = sptr(smem), sB = sA + 128 * 256;
    int tid = threadIdx.x, wid = tid >> 5, lane = tid & 31;
    load_tile<128, 256>(sA, g_at + blockIdx.x * 128 * 128, tid);
    load_tile<128, 256>(sB, g_wt[3], tid);
    cp_commit(); cp_wait<0>(); __syncthreads();
    int agrp = lane >> 3, lr = lane & 7;
    int mrow = wid * 16 + lr + ((agrp & 1) << 3);
    float acc[16][4];
#pragma unroll
    for (int i = 0; i < 16; i++) { acc[i][0] = acc[i][1] = acc[i][2] = acc[i][3] = 0.f; }
#pragma unroll
    for (int kk2 = 0; kk2 < 4; kk2++) {
        uint32_t a0[4], a1[4];
        ldsm4(a0, sA + sw_off(mrow, 4 * kk2 +     (agrp >> 1)));
        ldsm4(a1, sA + sw_off(mrow, 4 * kk2 + 2 + (agrp >> 1)));
#pragma unroll
        for (int nt = 0; nt < 16; nt++) {
            uint32_t b[4];
            ldsm4(b, sB + sw_off(nt * 8 + lr, 4 * kk2 + agrp));
            mma16816(acc[nt], a0, b);
            mma16816(acc[nt], a1, b + 2);
        }
    }
    int r0 = blockIdx.x * 128 + wid * 16 + (lane >> 2);
    int cb = (lane & 3) * 2;
#pragma unroll
    for (int nt = 0; nt < 16; nt++) {
        int col = nt * 8 + cb;
        float b0 = bo[col], b1 = bo[col + 1];
        *reinterpret_cast<float2*>(out + r0 * 128 + col) =
            make_float2(acc[nt][0] + b0 + x[r0 * 128 + col],
                        acc[nt][1] + b1 + x[r0 * 128 + col + 1]);
        *reinterpret_cast<float2*>(out + (r0 + 8) * 128 + col) =
            make_float2(acc[nt][2] + b0 + x[(r0 + 8) * 128 + col],
                        acc[nt][3] + b1 + x[(r0 + 8) * 128 + col + 1]);
    }
}

// ---------------- launch ----------------
extern "C" void kernel_launch(void* const* d_in, const int* in_sizes, int n_in,
                              void* d_out, int out_size) {
    (void)in_sizes; (void)n_in; (void)out_size;
    const float* x     = (const float*)d_in[0];
    const float* gamma = (const float*)d_in[1];
    const float* wq = (const float*)d_in[2];
    const float* bq = (const float*)d_in[3];
    const float* wk = (const float*)d_in[4];
    const float* bk = (const float*)d_in[5];
    const float* wv = (const float*)d_in[6];
    const float* bv = (const float*)d_in[7];
    const float* wo = (const float*)d_in[8];
    const float* bo = (const float*)d_in[9];
    float* out = (float*)d_out;

    cudaFuncSetAttribute(k_qkv,   cudaFuncAttributeMaxDynamicSharedMemorySize, 65536);
    cudaFuncSetAttribute(k_oproj, cudaFuncAttributeMaxDynamicSharedMemorySize, 65536);
    cudaFuncSetAttribute(k_attn,  cudaFuncAttributeMaxDynamicSharedMemorySize, 163840);

    k_norm <<<S / 8, 256>>>(x, gamma);
    k_wconv<<<dim3(64, 4), 256>>>(wq, wk, wv, wo);
    k_qkv  <<<dim3(S / 128, 3), 256, 65536>>>(bq, bk, bv);
    k_attn <<<NUNITS, 256, 163840>>>();
    k_comb <<<256, 256>>>();
    k_oproj<<<S / 128, 256, 65536>>>(bo, x, out);
}